// round 11
// baseline (speedup 1.0000x reference)
#include <cuda_runtime.h>
#include <math.h>

#define D  4096
#define K2 8192
#define KS 32          // split-K chunks (proven gemv shape)
#define KC (K2 / KS)   // 256 rows per chunk
#define NB 8           // n-chunks of 512 cols -> grid (8,32,4) = 1024 blocks
#define GPG (NB * KS)  // gemv blocks per gate = 256

// ---------------- scratch (no device allocation allowed) ----------------
__device__ float    g_partial[4 * KS * D];   // split-K partial sums (2 MB, L2-resident)
__device__ float    g_qa[4 * D];             // quantized gate activations
__device__ unsigned g_gate_ctr[4];           // per-gate completion counters (zero-init)
__device__ unsigned g_done;                  // finisher completion counter (zero-init)

// ---------------- helpers ----------------
__device__ __forceinline__ float mkscale(float maxabs) {
    return (maxabs > 0.0f) ? (maxabs / 127.0f) : 1.0f;
}
__device__ __forceinline__ float qvalr(float x, float scale, float rscale) {
    float r = rintf(x * rscale);
    r = fminf(fmaxf(r, -127.0f), 127.0f);
    return r * scale;
}
__device__ __forceinline__ float sigm(float x) {
    return __fdividef(1.0f, 1.0f + __expf(-x));
}
__device__ __forceinline__ float max4abs(float4 v) {
    return fmaxf(fmaxf(fabsf(v.x), fabsf(v.y)), fmaxf(fabsf(v.z), fabsf(v.w)));
}

// Block-wide max (signed-safe), blockDim.x = 256.
__device__ __forceinline__ float blockMax(float v) {
    __shared__ float s[8];
    const unsigned full = 0xffffffffu;
    #pragma unroll
    for (int o = 16; o; o >>= 1) v = fmaxf(v, __shfl_xor_sync(full, v, o));
    int lane = threadIdx.x & 31, w = threadIdx.x >> 5;
    if (lane == 0) s[w] = v;
    __syncthreads();
    if (w == 0) {
        float r = (lane < 8) ? s[lane] : -INFINITY;
        #pragma unroll
        for (int o = 4; o; o >>= 1) r = fmaxf(r, __shfl_xor_sync(full, r, o));
        if (lane == 0) s[0] = r;
    }
    __syncthreads();
    float out = s[0];
    __syncthreads();
    return out;
}
// Two block maxes sharing one barrier set.
__device__ __forceinline__ float2 blockMax2(float a, float b) {
    __shared__ float sa[8], sb[8];
    const unsigned full = 0xffffffffu;
    #pragma unroll
    for (int o = 16; o; o >>= 1) {
        a = fmaxf(a, __shfl_xor_sync(full, a, o));
        b = fmaxf(b, __shfl_xor_sync(full, b, o));
    }
    int lane = threadIdx.x & 31, w = threadIdx.x >> 5;
    if (lane == 0) { sa[w] = a; sb[w] = b; }
    __syncthreads();
    if (w == 0) {
        float ra = (lane < 8) ? sa[lane] : -INFINITY;
        float rb = (lane < 8) ? sb[lane] : -INFINITY;
        #pragma unroll
        for (int o = 4; o; o >>= 1) {
            ra = fmaxf(ra, __shfl_xor_sync(full, ra, o));
            rb = fmaxf(rb, __shfl_xor_sync(full, rb, o));
        }
        if (lane == 0) { sa[0] = ra; sb[0] = rb; }
    }
    __syncthreads();
    float2 out = make_float2(sa[0], sb[0]);
    __syncthreads();
    return out;
}

// ---------------- fused kernel: GEMV + per-gate finisher + tail ----------------
// grid (8,32,4) x 256 thr — the proven ~78us HBM-saturating shape.
// __launch_bounds__(256, 8): pin regs <= 32 so finisher code can't hurt gemv occupancy.
__global__ void __launch_bounds__(256, 8) fused_kernel(
    const float* __restrict__ x,  const float* __restrict__ h,
    const float* __restrict__ Wf, const float* __restrict__ Wi,
    const float* __restrict__ Wc, const float* __restrict__ Wo,
    const float* __restrict__ bf, const float* __restrict__ bi,
    const float* __restrict__ bc, const float* __restrict__ bo,
    const float* __restrict__ c_in, float* __restrict__ out)
{
    __shared__ float xs[KC];
    __shared__ float spre[D];          // finisher scratch (16 KB)
    __shared__ unsigned s_tk;

    const int g  = blockIdx.z;
    const int kc = blockIdx.y;
    const int n0 = blockIdx.x * 512 + threadIdx.x * 2;
    const int k0 = kc * KC;
    const int t  = threadIdx.x;

    const float* W = (g == 0) ? Wf : (g == 1) ? Wi : (g == 2) ? Wc : Wo;
    const float* b = (g == 0) ? bf : (g == 1) ? bi : (g == 2) ? bc : bo;

    // ---- gemv phase (unchanged from the 77.8us config) ----
    float lm = 0.0f;
    #pragma unroll
    for (int j = 0; j < K2 / 256; j++) {
        int i = t + j * 256;
        float v = (i < D) ? h[i] : x[i - D];
        lm = fmaxf(lm, fabsf(v));
    }
    float scale = mkscale(blockMax(lm));
    float rs = 1.0f / scale;
    {
        int gi = k0 + t;
        float v = (gi < D) ? h[gi] : x[gi - D];
        xs[t] = qvalr(v, scale, rs);
    }
    __syncthreads();

    const float2* p = reinterpret_cast<const float2*>(W + (size_t)k0 * D) + (n0 >> 1);
    const int rowstride = D / 2;
    float2 acc = make_float2(0.f, 0.f);
    #pragma unroll 8
    for (int i = 0; i < KC; i++) {
        float2 w = __ldcs(p + (size_t)i * rowstride);
        float  xv = xs[i];
        acc.x = fmaf(xv, w.x, acc.x);
        acc.y = fmaf(xv, w.y, acc.y);
    }
    *reinterpret_cast<float2*>(&g_partial[(size_t)(g * KS + kc) * D + n0]) = acc;

    // ---- per-gate ticket: last of this gate's 256 blocks becomes the finisher ----
    __threadfence();
    __syncthreads();
    if (t == 0) s_tk = atomicAdd(&g_gate_ctr[g], 1u);
    __syncthreads();
    if (s_tk != GPG - 1) return;
    __threadfence();                                  // acquire: all partials visible

    // ================= gate finisher (256 threads, 16 elems/thread) =================
    float4* spre4 = reinterpret_cast<float4*>(spre);
    const float4* gp4 = reinterpret_cast<const float4*>(g_partial) + (size_t)g * KS * (D / 4);
    const float4* b4  = reinterpret_cast<const float4*>(b);

    // 1) split-K reduce -> spre; block-local max|acc|, max|b|
    float lmacc = 0.0f, lb = 0.0f;
    #pragma unroll
    for (int e = 0; e < 4; e++) {
        int i4 = e * 256 + t;
        const float4* pb = gp4 + i4;
        float4 s0 = make_float4(0.f,0.f,0.f,0.f), s1 = make_float4(0.f,0.f,0.f,0.f);
        #pragma unroll 4
        for (int ks = 0; ks < KS; ks += 2) {
            float4 v0 = __ldcg(pb + (size_t)(ks + 0) * (D / 4));
            float4 v1 = __ldcg(pb + (size_t)(ks + 1) * (D / 4));
            s0.x += v0.x; s0.y += v0.y; s0.z += v0.z; s0.w += v0.w;
            s1.x += v1.x; s1.y += v1.y; s1.z += v1.z; s1.w += v1.w;
        }
        float4 s = make_float4(s0.x + s1.x, s0.y + s1.y, s0.z + s1.z, s0.w + s1.w);
        spre4[i4] = s;
        lmacc = fmaxf(lmacc, max4abs(s));
        lb    = fmaxf(lb, max4abs(__ldg(b4 + i4)));
    }
    __syncthreads();
    float2 mm = blockMax2(lmacc, lb);
    float sm = mkscale(mm.x), rsm = 1.0f / sm;
    float sb = mkscale(mm.y), rsb = 1.0f / sb;

    // 2) y = Q(x@w) + Q(b) -> spre; signed max / min
    float ymx = -INFINITY, ymn = INFINITY;
    #pragma unroll
    for (int e = 0; e < 4; e++) {
        int i4 = e * 256 + t;
        float4 a = spre4[i4];
        float4 bv = __ldg(b4 + i4);
        float4 y;
        y.x = qvalr(a.x, sm, rsm) + qvalr(bv.x, sb, rsb);
        y.y = qvalr(a.y, sm, rsm) + qvalr(bv.y, sb, rsb);
        y.z = qvalr(a.z, sm, rsm) + qvalr(bv.z, sb, rsb);
        y.w = qvalr(a.w, sm, rsm) + qvalr(bv.w, sb, rsb);
        spre4[i4] = y;
        ymx = fmaxf(ymx, fmaxf(fmaxf(y.x, y.y), fmaxf(y.z, y.w)));
        ymn = fminf(ymn, fminf(fminf(y.x, y.y), fminf(y.z, y.w)));
    }
    float2 ym = blockMax2(ymx, -ymn);
    float sy = mkscale(fmaxf(ym.x, ym.y)), rsy = 1.0f / sy;
    // analytic activation scale (monotone fn -> evaluate at argmax)
    float sa = (g == 2) ? mkscale(tanhf(qvalr(fmaxf(ym.x, ym.y), sy, rsy)))
                        : mkscale(sigm(qvalr(ym.x, sy, rsy)));
    float rsa = 1.0f / sa;

    // 3) qa = Q(act(Q(y))) -> g_qa
    float4* gq4 = reinterpret_cast<float4*>(g_qa);
    #pragma unroll
    for (int e = 0; e < 4; e++) {
        int i4 = e * 256 + t;
        float4 y = spre4[i4];
        float4 q;
        float* yp = &y.x; float* qp = &q.x;
        #pragma unroll
        for (int j = 0; j < 4; j++) {
            float yq = qvalr(yp[j], sy, rsy);
            float av = (g == 2) ? tanhf(yq) : sigm(yq);
            qp[j] = qvalr(av, sa, rsa);
        }
        gq4[(size_t)g * (D / 4) + i4] = q;
    }

    // ---- finisher ticket: last of 4 runs the tail ----
    __threadfence();
    __syncthreads();
    if (t == 0) s_tk = atomicAdd(&g_done, 1u);
    __syncthreads();
    if (s_tk != 3u) return;
    __threadfence();                                  // acquire: all qa visible

    // ================= tail (one block, 16 elems/thread, smem-staged) =================
    const float4* c4 = reinterpret_cast<const float4*>(c_in);

    // round C: max|mem|, max|cf|
    float lmem = 0.f, lcf = 0.f;
    #pragma unroll
    for (int e = 0; e < 4; e++) {
        int i4 = e * 256 + t;
        float4 qf = __ldcg(gq4 + 0 * (D / 4) + i4);
        float4 qi = __ldcg(gq4 + 1 * (D / 4) + i4);
        float4 qc = __ldcg(gq4 + 2 * (D / 4) + i4);
        float4 cv = __ldg(c4 + i4);
        float4 mem = make_float4(qc.x*qi.x, qc.y*qi.y, qc.z*qi.z, qc.w*qi.w);
        float4 cf  = make_float4(cv.x*qf.x, cv.y*qf.y, cv.z*qf.z, cv.w*qf.w);
        lmem = fmaxf(lmem, max4abs(mem));
        lcf  = fmaxf(lcf,  max4abs(cf));
    }
    float2 mc = blockMax2(lmem, lcf);
    float s_mem = mkscale(mc.x), r_mem = 1.0f / s_mem;
    float s_cf  = mkscale(mc.y), r_cf  = 1.0f / s_cf;

    // round D: cn -> spre; max|cn|
    float lcn = 0.f;
    #pragma unroll
    for (int e = 0; e < 4; e++) {
        int i4 = e * 256 + t;
        float4 qf = __ldcg(gq4 + 0 * (D / 4) + i4);
        float4 qi = __ldcg(gq4 + 1 * (D / 4) + i4);
        float4 qc = __ldcg(gq4 + 2 * (D / 4) + i4);
        float4 cv = __ldg(c4 + i4);
        float4 cn;
        cn.x = qvalr(cv.x*qf.x, s_cf, r_cf) + qvalr(qc.x*qi.x, s_mem, r_mem);
        cn.y = qvalr(cv.y*qf.y, s_cf, r_cf) + qvalr(qc.y*qi.y, s_mem, r_mem);
        cn.z = qvalr(cv.z*qf.z, s_cf, r_cf) + qvalr(qc.z*qi.z, s_mem, r_mem);
        cn.w = qvalr(cv.w*qf.w, s_cf, r_cf) + qvalr(qc.w*qi.w, s_mem, r_mem);
        spre4[i4] = cn;
        lcn = fmaxf(lcn, max4abs(cn));
    }
    __syncthreads();
    float cnmax = blockMax(lcn);
    float s_cn = mkscale(cnmax), r_cn = 1.0f / s_cn;
    float s_t  = mkscale(tanhf(qvalr(cnmax, s_cn, r_cn)));   // analytic tanh scale
    float r_t  = 1.0f / s_t;

    // round E: hv -> spre; max|hv|
    float lh = 0.f;
    #pragma unroll
    for (int e = 0; e < 4; e++) {
        int i4 = e * 256 + t;
        float4 cn = spre4[i4];
        float4 zo = __ldcg(gq4 + 3 * (D / 4) + i4);
        float4 hv;
        hv.x = zo.x * qvalr(tanhf(qvalr(cn.x, s_cn, r_cn)), s_t, r_t);
        hv.y = zo.y * qvalr(tanhf(qvalr(cn.y, s_cn, r_cn)), s_t, r_t);
        hv.z = zo.z * qvalr(tanhf(qvalr(cn.z, s_cn, r_cn)), s_t, r_t);
        hv.w = zo.w * qvalr(tanhf(qvalr(cn.w, s_cn, r_cn)), s_t, r_t);
        spre4[i4] = hv;
        lh = fmaxf(lh, max4abs(hv));
    }
    __syncthreads();
    float s_h = mkscale(blockMax(lh)), r_h = 1.0f / s_h;

    float4* out4 = reinterpret_cast<float4*>(out);
    #pragma unroll
    for (int e = 0; e < 4; e++) {
        int i4 = e * 256 + t;
        float4 hv = spre4[i4];
        float4 o;
        o.x = qvalr(hv.x, s_h, r_h); o.y = qvalr(hv.y, s_h, r_h);
        o.z = qvalr(hv.z, s_h, r_h); o.w = qvalr(hv.w, s_h, r_h);
        out4[i4] = o;
    }

    // reset all counters for the next graph replay (only this block is alive here)
    __syncthreads();
    if (t == 0) {
        g_gate_ctr[0] = 0u; g_gate_ctr[1] = 0u;
        g_gate_ctr[2] = 0u; g_gate_ctr[3] = 0u;
        g_done = 0u;
        __threadfence();
    }
}

// ---------------- launch ----------------
extern "C" void kernel_launch(void* const* d_in, const int* in_sizes, int n_in,
                              void* d_out, int out_size)
{
    const float* x  = (const float*)d_in[0];
    const float* c  = (const float*)d_in[1];
    const float* h  = (const float*)d_in[2];
    const float* Wf = (const float*)d_in[3];
    const float* bf = (const float*)d_in[4];
    const float* Wi = (const float*)d_in[5];
    const float* bi = (const float*)d_in[6];
    const float* Wc = (const float*)d_in[7];
    const float* bc = (const float*)d_in[8];
    const float* Wo = (const float*)d_in[9];
    const float* bo = (const float*)d_in[10];

    dim3 gridB(NB, KS, 4);                     // (8, 32, 4) = 1024 blocks
    fused_kernel<<<gridB, 256>>>(x, h, Wf, Wi, Wc, Wo,
                                 bf, bi, bc, bo, c, (float*)d_out);
}

// round 12
// speedup vs baseline: 1.1130x; 1.1130x over previous
#include <cuda_runtime.h>
#include <math.h>

#define D  4096
#define K2 8192
#define KS 32          // split-K chunks (proven gemv shape)
#define KC (K2 / KS)   // 256 rows per chunk
#define NB 8           // n-chunks of 512 cols -> grid (8,32,4) = 1024 blocks

// ---------------- scratch (no device allocation allowed) ----------------
__device__ float    g_partial[4 * KS * D];   // split-K partial sums (2 MB, L2-resident)
__device__ float    g_pre[4 * D];            // combined per-gate matmul results (64 KB)
__device__ float    g_qa[4 * D];             // quantized gate activations
__device__ unsigned g_nb_ctr[4 * NB];        // per-(gate,nchunk) tickets (zero-init)
__device__ unsigned g_done;                  // gate-block completion counter (zero-init)

// ---------------- helpers ----------------
__device__ __forceinline__ float mkscale(float maxabs) {
    // matches jnp.where(max_abs > 0, max_abs / 127.0, 1.0) in fp32
    return (maxabs > 0.0f) ? (maxabs / 127.0f) : 1.0f;
}
__device__ __forceinline__ float qvalr(float x, float scale, float rscale) {
    float r = rintf(x * rscale);
    r = fminf(fmaxf(r, -127.0f), 127.0f);
    return r * scale;
}
__device__ __forceinline__ float sigm(float x) {
    return __fdividef(1.0f, 1.0f + __expf(-x));
}
__device__ __forceinline__ float max4abs(float4 v) {
    return fmaxf(fmaxf(fabsf(v.x), fabsf(v.y)), fmaxf(fabsf(v.z), fabsf(v.w)));
}

// Block-wide max (signed-safe). blockDim.x multiple of 32.
__device__ __forceinline__ float blockMax(float v) {
    __shared__ float s[32];
    const unsigned full = 0xffffffffu;
    #pragma unroll
    for (int o = 16; o; o >>= 1) v = fmaxf(v, __shfl_xor_sync(full, v, o));
    int lane = threadIdx.x & 31, w = threadIdx.x >> 5;
    int nw = (blockDim.x + 31) >> 5;
    if (lane == 0) s[w] = v;
    __syncthreads();
    if (w == 0) {
        float r = (lane < nw) ? s[lane] : -INFINITY;
        #pragma unroll
        for (int o = 16; o; o >>= 1) r = fmaxf(r, __shfl_xor_sync(full, r, o));
        if (lane == 0) s[0] = r;
    }
    __syncthreads();
    float out = s[0];
    __syncthreads();
    return out;
}
// Two block maxes sharing one barrier set.
__device__ __forceinline__ float2 blockMax2(float a, float b) {
    __shared__ float sa[32], sb[32];
    const unsigned full = 0xffffffffu;
    #pragma unroll
    for (int o = 16; o; o >>= 1) {
        a = fmaxf(a, __shfl_xor_sync(full, a, o));
        b = fmaxf(b, __shfl_xor_sync(full, b, o));
    }
    int lane = threadIdx.x & 31, w = threadIdx.x >> 5;
    int nw = (blockDim.x + 31) >> 5;
    if (lane == 0) { sa[w] = a; sb[w] = b; }
    __syncthreads();
    if (w == 0) {
        float ra = (lane < nw) ? sa[lane] : -INFINITY;
        float rb = (lane < nw) ? sb[lane] : -INFINITY;
        #pragma unroll
        for (int o = 16; o; o >>= 1) {
            ra = fmaxf(ra, __shfl_xor_sync(full, ra, o));
            rb = fmaxf(rb, __shfl_xor_sync(full, rb, o));
        }
        if (lane == 0) { sa[0] = ra; sb[0] = rb; }
    }
    __syncthreads();
    float2 out = make_float2(sa[0], sb[0]);
    __syncthreads();
    return out;
}

// ---------------- kernel 1: GEMV + distributed split-K combine ----------------
// grid (8,32,4) x 256 thr — the proven HBM-saturating shape. Tiny smem, no big scratch.
// Last kc-block of each (gate, nchunk) combines its 32 partials into g_pre
// (registers only, fixed order -> deterministic), overlapped with the stream.
__global__ void __launch_bounds__(256, 8) gemv_kernel(
    const float* __restrict__ x,  const float* __restrict__ h,
    const float* __restrict__ Wf, const float* __restrict__ Wi,
    const float* __restrict__ Wc, const float* __restrict__ Wo)
{
    __shared__ float xs[KC];
    __shared__ unsigned s_tk;
    const int g  = blockIdx.z;
    const int kc = blockIdx.y;
    const int nb = blockIdx.x;
    const int n0 = nb * 512 + threadIdx.x * 2;
    const int k0 = kc * KC;
    const int t  = threadIdx.x;

    const float* W = (g == 0) ? Wf : (g == 1) ? Wi : (g == 2) ? Wc : Wo;

    // global max of |[h, x]| (identical in every block; overlapped with HBM stream)
    float lm = 0.0f;
    #pragma unroll
    for (int j = 0; j < K2 / 256; j++) {
        int i = t + j * 256;
        float v = (i < D) ? h[i] : x[i - D];
        lm = fmaxf(lm, fabsf(v));
    }
    float scale = mkscale(blockMax(lm));
    float rs = 1.0f / scale;
    {
        int gi = k0 + t;
        float v = (gi < D) ? h[gi] : x[gi - D];
        xs[t] = qvalr(v, scale, rs);
    }
    __syncthreads();

    const float2* p = reinterpret_cast<const float2*>(W + (size_t)k0 * D) + (n0 >> 1);
    const int rowstride = D / 2;
    float2 acc = make_float2(0.f, 0.f);
    #pragma unroll 8
    for (int i = 0; i < KC; i++) {
        float2 w = __ldcs(p + (size_t)i * rowstride);   // streaming: read-once weights
        float  xv = xs[i];
        acc.x = fmaf(xv, w.x, acc.x);
        acc.y = fmaf(xv, w.y, acc.y);
    }
    *reinterpret_cast<float2*>(&g_partial[(size_t)(g * KS + kc) * D + n0]) = acc;

    // ---- per-(gate,nchunk) ticket: last of 32 kc-blocks combines ----
    __threadfence();                 // release: partial visible
    __syncthreads();
    if (t == 0) s_tk = atomicAdd(&g_nb_ctr[g * NB + nb], 1u);
    __syncthreads();
    if (s_tk != KS - 1) return;
    __threadfence();                 // acquire: all 32 partials of this (g,nb) visible

    // combine: 32 float2 loads per thread, 4 chains, fixed order (register-light)
    {
        const float2* pp = reinterpret_cast<const float2*>(g_partial + (size_t)g * KS * D)
                         + (n0 >> 1);
        float2 c0 = make_float2(0.f, 0.f), c1 = make_float2(0.f, 0.f);
        float2 c2 = make_float2(0.f, 0.f), c3 = make_float2(0.f, 0.f);
        #pragma unroll 4
        for (int ks = 0; ks < KS; ks += 4) {
            float2 v0 = __ldcg(pp + (size_t)(ks + 0) * (D / 2));
            float2 v1 = __ldcg(pp + (size_t)(ks + 1) * (D / 2));
            float2 v2 = __ldcg(pp + (size_t)(ks + 2) * (D / 2));
            float2 v3 = __ldcg(pp + (size_t)(ks + 3) * (D / 2));
            c0.x += v0.x; c0.y += v0.y;  c1.x += v1.x; c1.y += v1.y;
            c2.x += v2.x; c2.y += v2.y;  c3.x += v3.x; c3.y += v3.y;
        }
        float2 s;
        s.x = (c0.x + c1.x) + (c2.x + c3.x);
        s.y = (c0.y + c1.y) + (c2.y + c3.y);
        *reinterpret_cast<float2*>(&g_pre[(size_t)g * D + n0]) = s;
    }
}

// ---------------- kernel 2: gate chain (4 blocks) + fused tail in last-done block ----
// R7 sync topology (single global handshake); split-K reduce already done in gemv.
__global__ void __launch_bounds__(1024, 1)
gate_tail_kernel(const float* __restrict__ bf, const float* __restrict__ bi,
                 const float* __restrict__ bc, const float* __restrict__ bo,
                 const float* __restrict__ c_in, float* __restrict__ out)
{
    const int g = blockIdx.x;
    const float* b = (g == 0) ? bf : (g == 1) ? bi : (g == 2) ? bc : bo;
    const int t = threadIdx.x;

    // preload c + bias (eventual tail winner has them in registers)
    float4 cv = reinterpret_cast<const float4*>(c_in)[t];
    float4 bv = reinterpret_cast<const float4*>(b)[t];

    // combined matmul result: ONE float4 load (reduce happened in gemv)
    float4 acc = reinterpret_cast<const float4*>(g_pre)[(size_t)g * (D / 4) + t];

    float2 mm = blockMax2(max4abs(acc), max4abs(bv));
    float sm = mkscale(mm.x), rsm = 1.0f / sm;     // Q(x@w) scale
    float sb = mkscale(mm.y), rsb = 1.0f / sb;     // Q(b) scale

    float y[4] = { qvalr(acc.x, sm, rsm) + qvalr(bv.x, sb, rsb),
                   qvalr(acc.y, sm, rsm) + qvalr(bv.y, sb, rsb),
                   qvalr(acc.z, sm, rsm) + qvalr(bv.z, sb, rsb),
                   qvalr(acc.w, sm, rsm) + qvalr(bv.w, sb, rsb) };

    float lmax = fmaxf(fmaxf(y[0], y[1]), fmaxf(y[2], y[3]));
    float lmin = fminf(fminf(y[0], y[1]), fminf(y[2], y[3]));
    float2 ym = blockMax2(lmax, -lmin);            // (max y, -min y)
    float sy  = mkscale(fmaxf(ym.x, ym.y));
    float rsy = 1.0f / sy;

    // analytic activation scale (monotone functions -> evaluate at argmax)
    float sa;
    if (g == 2) {
        sa = mkscale(tanhf(qvalr(fmaxf(ym.x, ym.y), sy, rsy)));  // tanh odd+monotone
    } else {
        sa = mkscale(sigm(qvalr(ym.x, sy, rsy)));                // sigmoid increasing, >0
    }
    float rsa = 1.0f / sa;

    float4 qa;
    float* qp = &qa.x;
    #pragma unroll
    for (int j = 0; j < 4; j++) {
        float yq = qvalr(y[j], sy, rsy);                 // Q(Q(x@w)+Q(b))
        float a  = (g == 2) ? tanhf(yq) : sigm(yq);
        qp[j] = qvalr(a, sa, rsa);                       // Q(activation)
    }
    reinterpret_cast<float4*>(g_qa)[(size_t)g * (D / 4) + t] = qa;

    // --- last-done handshake: the 4th block to finish runs the tail inline ---
    __shared__ unsigned s_ticket;
    __threadfence();                 // release: qa visible
    __syncthreads();
    if (t == 0) s_ticket = atomicAdd(&g_done, 1u);
    __syncthreads();
    if (s_ticket != 3u) return;
    __threadfence();                 // acquire: other blocks' qa visible

    // --- tail: LSTM state update (this block only; own gate's qa in regs) ---
    const float4* qa4 = reinterpret_cast<const float4*>(g_qa);
    float4 zf = (g == 0) ? qa : qa4[0 * (D / 4) + t];
    float4 zi = (g == 1) ? qa : qa4[1 * (D / 4) + t];
    float4 z  = (g == 2) ? qa : qa4[2 * (D / 4) + t];
    float4 zo = (g == 3) ? qa : qa4[3 * (D / 4) + t];

    float mem[4] = { z.x * zi.x,  z.y * zi.y,  z.z * zi.z,  z.w * zi.w };
    float cf [4] = { cv.x * zf.x, cv.y * zf.y, cv.z * zf.z, cv.w * zf.w };

    float lm = 0.f, lc = 0.f;
    #pragma unroll
    for (int j = 0; j < 4; j++) { lm = fmaxf(lm, fabsf(mem[j])); lc = fmaxf(lc, fabsf(cf[j])); }
    float2 mc = blockMax2(lm, lc);
    float s_mem = mkscale(mc.x), r_mem = 1.0f / s_mem;
    float s_cf  = mkscale(mc.y), r_cf  = 1.0f / s_cf;

    float cn[4]; float ln = 0.f;
    #pragma unroll
    for (int j = 0; j < 4; j++) {
        cn[j] = qvalr(cf[j], s_cf, r_cf) + qvalr(mem[j], s_mem, r_mem);  // Q(c*zf)+Q(z*zi)
        ln = fmaxf(ln, fabsf(cn[j]));
    }
    float cnmax = blockMax(ln);
    float s_cn  = mkscale(cnmax), r_cn = 1.0f / s_cn;

    // analytic: max|tanh(Q(cn))| = tanh(Q(max|cn|))
    float s_t = mkscale(tanhf(qvalr(cnmax, s_cn, r_cn)));
    float r_t = 1.0f / s_t;

    float zop[4] = { zo.x, zo.y, zo.z, zo.w };
    float hv[4]; float lh = 0.f;
    #pragma unroll
    for (int j = 0; j < 4; j++) {
        float cq = qvalr(cn[j], s_cn, r_cn);             // c_new
        float tq = qvalr(tanhf(cq), s_t, r_t);           // Q(tanh(c_new))
        hv[j] = zop[j] * tq;
        lh = fmaxf(lh, fabsf(hv[j]));
    }
    float s_h = mkscale(blockMax(lh)), r_h = 1.0f / s_h;

    float4 o;
    o.x = qvalr(hv[0], s_h, r_h); o.y = qvalr(hv[1], s_h, r_h);
    o.z = qvalr(hv[2], s_h, r_h); o.w = qvalr(hv[3], s_h, r_h);
    reinterpret_cast<float4*>(out)[t] = o;

    // reset ALL tickets for the next graph replay (only this block is alive here)
    __syncthreads();
    if (t < 4 * NB) g_nb_ctr[t] = 0u;
    if (t == 0)     g_done = 0u;
    __threadfence();
}

// ---------------- launch ----------------
extern "C" void kernel_launch(void* const* d_in, const int* in_sizes, int n_in,
                              void* d_out, int out_size)
{
    const float* x  = (const float*)d_in[0];
    const float* c  = (const float*)d_in[1];
    const float* h  = (const float*)d_in[2];
    const float* Wf = (const float*)d_in[3];
    const float* bf = (const float*)d_in[4];
    const float* Wi = (const float*)d_in[5];
    const float* bi = (const float*)d_in[6];
    const float* Wc = (const float*)d_in[7];
    const float* bc = (const float*)d_in[8];
    const float* Wo = (const float*)d_in[9];
    const float* bo = (const float*)d_in[10];

    dim3 gridB(NB, KS, 4);                     // (8, 32, 4) = 1024 blocks
    gemv_kernel<<<gridB, 256>>>(x, h, Wf, Wi, Wc, Wo);

    gate_tail_kernel<<<4, 1024>>>(bf, bi, bc, bo, c, (float*)d_out);
}

// round 13
// speedup vs baseline: 1.1377x; 1.0222x over previous
#include <cuda_runtime.h>
#include <math.h>

#define D  4096
#define K2 8192
#define KS 32          // split-K chunks (proven gemv shape)
#define KC (K2 / KS)   // 256 rows per chunk
#define NB 8           // n-chunks of 512 cols -> grid (8,32,4) = 1024 blocks
#define MG 8           // merge groups per (gate, nchunk): KS/4

// ---------------- scratch (no device allocation allowed) ----------------
__device__ float    g_partial[4 * KS * D];   // staged per-kc partials (2 MB)
__device__ float    g_pre8[4 * MG * D];      // 4-way merged partials (512 KB)
__device__ float    g_qa[4 * D];             // quantized gate activations
__device__ unsigned g_mrg[4 * NB * MG];      // 4-way merge tickets (zero-init, 256)
__device__ unsigned g_done;                  // gate-block completion counter (zero-init)

// ---------------- helpers ----------------
__device__ __forceinline__ float mkscale(float maxabs) {
    // matches jnp.where(max_abs > 0, max_abs / 127.0, 1.0) in fp32
    return (maxabs > 0.0f) ? (maxabs / 127.0f) : 1.0f;
}
__device__ __forceinline__ float qvalr(float x, float scale, float rscale) {
    float r = rintf(x * rscale);
    r = fminf(fmaxf(r, -127.0f), 127.0f);
    return r * scale;
}
__device__ __forceinline__ float sigm(float x) {
    return __fdividef(1.0f, 1.0f + __expf(-x));
}
__device__ __forceinline__ float max4abs(float4 v) {
    return fmaxf(fmaxf(fabsf(v.x), fabsf(v.y)), fmaxf(fabsf(v.z), fabsf(v.w)));
}

// Block-wide max (signed-safe). blockDim.x multiple of 32.
__device__ __forceinline__ float blockMax(float v) {
    __shared__ float s[32];
    const unsigned full = 0xffffffffu;
    #pragma unroll
    for (int o = 16; o; o >>= 1) v = fmaxf(v, __shfl_xor_sync(full, v, o));
    int lane = threadIdx.x & 31, w = threadIdx.x >> 5;
    int nw = (blockDim.x + 31) >> 5;
    if (lane == 0) s[w] = v;
    __syncthreads();
    if (w == 0) {
        float r = (lane < nw) ? s[lane] : -INFINITY;
        #pragma unroll
        for (int o = 16; o; o >>= 1) r = fmaxf(r, __shfl_xor_sync(full, r, o));
        if (lane == 0) s[0] = r;
    }
    __syncthreads();
    float out = s[0];
    __syncthreads();
    return out;
}
// Two block maxes sharing one barrier set.
__device__ __forceinline__ float2 blockMax2(float a, float b) {
    __shared__ float sa[32], sb[32];
    const unsigned full = 0xffffffffu;
    #pragma unroll
    for (int o = 16; o; o >>= 1) {
        a = fmaxf(a, __shfl_xor_sync(full, a, o));
        b = fmaxf(b, __shfl_xor_sync(full, b, o));
    }
    int lane = threadIdx.x & 31, w = threadIdx.x >> 5;
    int nw = (blockDim.x + 31) >> 5;
    if (lane == 0) { sa[w] = a; sb[w] = b; }
    __syncthreads();
    if (w == 0) {
        float ra = (lane < nw) ? sa[lane] : -INFINITY;
        float rb = (lane < nw) ? sb[lane] : -INFINITY;
        #pragma unroll
        for (int o = 16; o; o >>= 1) {
            ra = fmaxf(ra, __shfl_xor_sync(full, ra, o));
            rb = fmaxf(rb, __shfl_xor_sync(full, rb, o));
        }
        if (lane == 0) { sa[0] = ra; sb[0] = rb; }
    }
    __syncthreads();
    float2 out = make_float2(sa[0], sb[0]);
    __syncthreads();
    return out;
}

// ---------------- kernel 1: GEMV + 4-way staged merge ----------------
// grid (8,32,4) x 256 thr — the proven HBM-saturating shape, tiny smem, regs~32.
// The 4th arriver of each kc-group-of-4 merges the 4 staged partials in fixed
// kc order (deterministic) with ONE parallel L2 round-trip — cheap even though
// it runs after the stream (R12 lesson: all blocks finish simultaneously).
__global__ void __launch_bounds__(256) gemv_kernel(
    const float* __restrict__ x,  const float* __restrict__ h,
    const float* __restrict__ Wf, const float* __restrict__ Wi,
    const float* __restrict__ Wc, const float* __restrict__ Wo)
{
    __shared__ float xs[KC];
    __shared__ unsigned s_tk;
    const int g  = blockIdx.z;
    const int kc = blockIdx.y;
    const int nb = blockIdx.x;
    const int n0 = nb * 512 + threadIdx.x * 2;
    const int k0 = kc * KC;
    const int t  = threadIdx.x;

    const float* W = (g == 0) ? Wf : (g == 1) ? Wi : (g == 2) ? Wc : Wo;

    // global max of |[h, x]| (identical in every block; overlapped with HBM stream)
    float lm = 0.0f;
    #pragma unroll
    for (int j = 0; j < K2 / 256; j++) {
        int i = t + j * 256;
        float v = (i < D) ? h[i] : x[i - D];
        lm = fmaxf(lm, fabsf(v));
    }
    float scale = mkscale(blockMax(lm));
    float rs = 1.0f / scale;
    {
        int gi = k0 + t;
        float v = (gi < D) ? h[gi] : x[gi - D];
        xs[t] = qvalr(v, scale, rs);
    }
    __syncthreads();

    const float2* p = reinterpret_cast<const float2*>(W + (size_t)k0 * D) + (n0 >> 1);
    const int rowstride = D / 2;
    float2 acc = make_float2(0.f, 0.f);
    #pragma unroll 16
    for (int i = 0; i < KC; i++) {
        float2 w = __ldcs(p + (size_t)i * rowstride);   // streaming: read-once weights
        float  xv = xs[i];
        acc.x = fmaf(xv, w.x, acc.x);
        acc.y = fmaf(xv, w.y, acc.y);
    }
    *reinterpret_cast<float2*>(&g_partial[(size_t)(g * KS + kc) * D + n0]) = acc;

    // ---- 4-way merge ticket: 4th arriver of {kb..kb+3} merges ----
    __threadfence();                 // release: staged partial visible
    __syncthreads();
    if (t == 0) s_tk = atomicAdd(&g_mrg[(g * NB + nb) * MG + (kc >> 2)], 1u);
    __syncthreads();
    if (s_tk != 3u) return;
    __threadfence();                 // acquire: partners' staged partials visible

    {
        const int kb = kc & ~3;      // group base kc
        const float* base = g_partial + (size_t)g * KS * D + n0;
        float2 v[4];
        #pragma unroll
        for (int k = 0; k < 4; k++) {
            if (kb + k == kc) v[k] = acc;   // own value already in registers
            else {
                const float2* q = reinterpret_cast<const float2*>(base + (size_t)(kb + k) * D);
                v[k] = __ldcg(q);
            }
        }
        float2 s;                    // fixed kc-order tree -> deterministic
        s.x = (v[0].x + v[1].x) + (v[2].x + v[3].x);
        s.y = (v[0].y + v[1].y) + (v[2].y + v[3].y);
        *reinterpret_cast<float2*>(&g_pre8[(size_t)(g * MG + (kc >> 2)) * D + n0]) = s;
    }
}

// ---------------- kernel 2: gate chain (4 blocks) + fused tail in last-done block ----
// R7 sync topology; reduce is now only 8 loads (4-way merge happened in gemv).
__global__ void __launch_bounds__(1024, 1)
gate_tail_kernel(const float* __restrict__ bf, const float* __restrict__ bi,
                 const float* __restrict__ bc, const float* __restrict__ bo,
                 const float* __restrict__ c_in, float* __restrict__ out)
{
    const int g = blockIdx.x;
    const float* b = (g == 0) ? bf : (g == 1) ? bi : (g == 2) ? bc : bo;
    const int t = threadIdx.x;

    // preload c + bias (eventual tail winner has them in registers)
    float4 cv = reinterpret_cast<const float4*>(c_in)[t];
    float4 bv = reinterpret_cast<const float4*>(b)[t];

    // --- reduce: 8 float4 loads, 4 chains, fixed order ---
    const float4* pp = reinterpret_cast<const float4*>(g_pre8)
                     + (size_t)g * MG * (D / 4) + t;
    float4 s0 = pp[0 * (D / 4)], s1 = pp[1 * (D / 4)];
    float4 s2 = pp[2 * (D / 4)], s3 = pp[3 * (D / 4)];
    float4 s4 = pp[4 * (D / 4)], s5 = pp[5 * (D / 4)];
    float4 s6 = pp[6 * (D / 4)], s7 = pp[7 * (D / 4)];
    float4 c0, c1, c2, c3, acc;
    c0.x = s0.x + s4.x; c0.y = s0.y + s4.y; c0.z = s0.z + s4.z; c0.w = s0.w + s4.w;
    c1.x = s1.x + s5.x; c1.y = s1.y + s5.y; c1.z = s1.z + s5.z; c1.w = s1.w + s5.w;
    c2.x = s2.x + s6.x; c2.y = s2.y + s6.y; c2.z = s2.z + s6.z; c2.w = s2.w + s6.w;
    c3.x = s3.x + s7.x; c3.y = s3.y + s7.y; c3.z = s3.z + s7.z; c3.w = s3.w + s7.w;
    acc.x = (c0.x + c1.x) + (c2.x + c3.x);
    acc.y = (c0.y + c1.y) + (c2.y + c3.y);
    acc.z = (c0.z + c1.z) + (c2.z + c3.z);
    acc.w = (c0.w + c1.w) + (c2.w + c3.w);

    float2 mm = blockMax2(max4abs(acc), max4abs(bv));
    float sm = mkscale(mm.x), rsm = 1.0f / sm;     // Q(x@w) scale
    float sb = mkscale(mm.y), rsb = 1.0f / sb;     // Q(b) scale

    float y[4] = { qvalr(acc.x, sm, rsm) + qvalr(bv.x, sb, rsb),
                   qvalr(acc.y, sm, rsm) + qvalr(bv.y, sb, rsb),
                   qvalr(acc.z, sm, rsm) + qvalr(bv.z, sb, rsb),
                   qvalr(acc.w, sm, rsm) + qvalr(bv.w, sb, rsb) };

    float lmax = fmaxf(fmaxf(y[0], y[1]), fmaxf(y[2], y[3]));
    float lmin = fminf(fminf(y[0], y[1]), fminf(y[2], y[3]));
    float2 ym = blockMax2(lmax, -lmin);            // (max y, -min y)
    float sy  = mkscale(fmaxf(ym.x, ym.y));
    float rsy = 1.0f / sy;

    // analytic activation scale (monotone functions -> evaluate at argmax)
    float sa;
    if (g == 2) {
        sa = mkscale(tanhf(qvalr(fmaxf(ym.x, ym.y), sy, rsy)));  // tanh odd+monotone
    } else {
        sa = mkscale(sigm(qvalr(ym.x, sy, rsy)));                // sigmoid increasing, >0
    }
    float rsa = 1.0f / sa;

    float4 qa;
    float* qp = &qa.x;
    #pragma unroll
    for (int j = 0; j < 4; j++) {
        float yq = qvalr(y[j], sy, rsy);                 // Q(Q(x@w)+Q(b))
        float a  = (g == 2) ? tanhf(yq) : sigm(yq);
        qp[j] = qvalr(a, sa, rsa);                       // Q(activation)
    }
    reinterpret_cast<float4*>(g_qa)[(size_t)g * (D / 4) + t] = qa;

    // --- last-done handshake: the 4th block to finish runs the tail inline ---
    __shared__ unsigned s_ticket;
    __threadfence();                 // release: qa visible
    __syncthreads();
    if (t == 0) s_ticket = atomicAdd(&g_done, 1u);
    __syncthreads();
    if (s_ticket != 3u) return;
    __threadfence();                 // acquire: other blocks' qa visible

    // --- tail: LSTM state update (this block only; own gate's qa in regs) ---
    const float4* qa4 = reinterpret_cast<const float4*>(g_qa);
    float4 zf = (g == 0) ? qa : qa4[0 * (D / 4) + t];
    float4 zi = (g == 1) ? qa : qa4[1 * (D / 4) + t];
    float4 z  = (g == 2) ? qa : qa4[2 * (D / 4) + t];
    float4 zo = (g == 3) ? qa : qa4[3 * (D / 4) + t];

    float mem[4] = { z.x * zi.x,  z.y * zi.y,  z.z * zi.z,  z.w * zi.w };
    float cf [4] = { cv.x * zf.x, cv.y * zf.y, cv.z * zf.z, cv.w * zf.w };

    float lm = 0.f, lc = 0.f;
    #pragma unroll
    for (int j = 0; j < 4; j++) { lm = fmaxf(lm, fabsf(mem[j])); lc = fmaxf(lc, fabsf(cf[j])); }
    float2 mc = blockMax2(lm, lc);
    float s_mem = mkscale(mc.x), r_mem = 1.0f / s_mem;
    float s_cf  = mkscale(mc.y), r_cf  = 1.0f / s_cf;

    float cn[4]; float ln = 0.f;
    #pragma unroll
    for (int j = 0; j < 4; j++) {
        cn[j] = qvalr(cf[j], s_cf, r_cf) + qvalr(mem[j], s_mem, r_mem);  // Q(c*zf)+Q(z*zi)
        ln = fmaxf(ln, fabsf(cn[j]));
    }
    float cnmax = blockMax(ln);
    float s_cn  = mkscale(cnmax), r_cn = 1.0f / s_cn;

    // analytic: max|tanh(Q(cn))| = tanh(Q(max|cn|))
    float s_t = mkscale(tanhf(qvalr(cnmax, s_cn, r_cn)));
    float r_t = 1.0f / s_t;

    float zop[4] = { zo.x, zo.y, zo.z, zo.w };
    float hv[4]; float lh = 0.f;
    #pragma unroll
    for (int j = 0; j < 4; j++) {
        float cq = qvalr(cn[j], s_cn, r_cn);             // c_new
        float tq = qvalr(tanhf(cq), s_t, r_t);           // Q(tanh(c_new))
        hv[j] = zop[j] * tq;
        lh = fmaxf(lh, fabsf(hv[j]));
    }
    float s_h = mkscale(blockMax(lh)), r_h = 1.0f / s_h;

    float4 o;
    o.x = qvalr(hv[0], s_h, r_h); o.y = qvalr(hv[1], s_h, r_h);
    o.z = qvalr(hv[2], s_h, r_h); o.w = qvalr(hv[3], s_h, r_h);
    reinterpret_cast<float4*>(out)[t] = o;

    // reset ALL tickets for the next graph replay (only this block is alive here)
    __syncthreads();
    if (t < 4 * NB * MG) g_mrg[t] = 0u;    // 256 entries
    if (t == 0)          g_done  = 0u;
    __threadfence();
}

// ---------------- launch ----------------
extern "C" void kernel_launch(void* const* d_in, const int* in_sizes, int n_in,
                              void* d_out, int out_size)
{
    const float* x  = (const float*)d_in[0];
    const float* c  = (const float*)d_in[1];
    const float* h  = (const float*)d_in[2];
    const float* Wf = (const float*)d_in[3];
    const float* bf = (const float*)d_in[4];
    const float* Wi = (const float*)d_in[5];
    const float* bi = (const float*)d_in[6];
    const float* Wc = (const float*)d_in[7];
    const float* bc = (const float*)d_in[8];
    const float* Wo = (const float*)d_in[9];
    const float* bo = (const float*)d_in[10];

    dim3 gridB(NB, KS, 4);                     // (8, 32, 4) = 1024 blocks
    gemv_kernel<<<gridB, 256>>>(x, h, Wf, Wi, Wc, Wo);

    gate_tail_kernel<<<4, 1024>>>(bf, bi, bc, bo, c, (float*)d_out);
}

// round 14
// speedup vs baseline: 1.1850x; 1.0415x over previous
#include <cuda_runtime.h>
#include <math.h>

#define D  4096
#define K2 8192
#define KS 32          // split-K chunks (proven gemv shape)
#define KC (K2 / KS)   // 256 rows per chunk
#define NB 8           // n-chunks of 512 cols -> grid (8,32,4) = 1024 blocks

// ---------------- scratch (no device allocation allowed) ----------------
__device__ float    g_pre[4 * D];    // atomically-accumulated matmul results (zero-init;
                                     // each gate_tail block re-zeroes its quarter)
__device__ float    g_qa[4 * D];     // quantized gate activations
__device__ unsigned g_done;          // gate-block completion counter (zero-init)

// ---------------- helpers ----------------
__device__ __forceinline__ float mkscale(float maxabs) {
    // matches jnp.where(max_abs > 0, max_abs / 127.0, 1.0) in fp32
    return (maxabs > 0.0f) ? (maxabs / 127.0f) : 1.0f;
}
__device__ __forceinline__ float qvalr(float x, float scale, float rscale) {
    float r = rintf(x * rscale);
    r = fminf(fmaxf(r, -127.0f), 127.0f);
    return r * scale;
}
__device__ __forceinline__ float sigm(float x) {
    return __fdividef(1.0f, 1.0f + __expf(-x));
}
__device__ __forceinline__ float max4abs(float4 v) {
    return fmaxf(fmaxf(fabsf(v.x), fabsf(v.y)), fmaxf(fabsf(v.z), fabsf(v.w)));
}

// Block-wide max (signed-safe). blockDim.x multiple of 32.
__device__ __forceinline__ float blockMax(float v) {
    __shared__ float s[32];
    const unsigned full = 0xffffffffu;
    #pragma unroll
    for (int o = 16; o; o >>= 1) v = fmaxf(v, __shfl_xor_sync(full, v, o));
    int lane = threadIdx.x & 31, w = threadIdx.x >> 5;
    int nw = (blockDim.x + 31) >> 5;
    if (lane == 0) s[w] = v;
    __syncthreads();
    if (w == 0) {
        float r = (lane < nw) ? s[lane] : -INFINITY;
        #pragma unroll
        for (int o = 16; o; o >>= 1) r = fmaxf(r, __shfl_xor_sync(full, r, o));
        if (lane == 0) s[0] = r;
    }
    __syncthreads();
    float out = s[0];
    __syncthreads();
    return out;
}
// Two block maxes sharing one barrier set.
__device__ __forceinline__ float2 blockMax2(float a, float b) {
    __shared__ float sa[32], sb[32];
    const unsigned full = 0xffffffffu;
    #pragma unroll
    for (int o = 16; o; o >>= 1) {
        a = fmaxf(a, __shfl_xor_sync(full, a, o));
        b = fmaxf(b, __shfl_xor_sync(full, b, o));
    }
    int lane = threadIdx.x & 31, w = threadIdx.x >> 5;
    int nw = (blockDim.x + 31) >> 5;
    if (lane == 0) { sa[w] = a; sb[w] = b; }
    __syncthreads();
    if (w == 0) {
        float ra = (lane < nw) ? sa[lane] : -INFINITY;
        float rb = (lane < nw) ? sb[lane] : -INFINITY;
        #pragma unroll
        for (int o = 16; o; o >>= 1) {
            ra = fmaxf(ra, __shfl_xor_sync(full, ra, o));
            rb = fmaxf(rb, __shfl_xor_sync(full, rb, o));
        }
        if (lane == 0) { sa[0] = ra; sb[0] = rb; }
    }
    __syncthreads();
    float2 out = make_float2(sa[0], sb[0]);
    __syncthreads();
    return out;
}

// ---------------- kernel 1: fused concat-quant + split-K GEMV (HBM-bound) ----------------
// grid (8,32,4) x 256 thr — the proven ~77.8us shape: tiny smem, regs~32, NO post-stream
// phase (R12/R13 lesson: all blocks finish together, post-stream work is serial + taxed).
// Partials are accumulated with fire-and-forget RED.ADD into g_pre — fully overlapped.
__global__ void __launch_bounds__(256) gemv_kernel(
    const float* __restrict__ x,  const float* __restrict__ h,
    const float* __restrict__ Wf, const float* __restrict__ Wi,
    const float* __restrict__ Wc, const float* __restrict__ Wo)
{
    __shared__ float xs[KC];
    const int g  = blockIdx.z;
    const int kc = blockIdx.y;
    const int n0 = blockIdx.x * 512 + threadIdx.x * 2;
    const int k0 = kc * KC;
    const int t  = threadIdx.x;

    const float* W = (g == 0) ? Wf : (g == 1) ? Wi : (g == 2) ? Wc : Wo;

    // global max of |[h, x]| (identical in every block; overlapped with HBM stream)
    float lm = 0.0f;
    #pragma unroll
    for (int j = 0; j < K2 / 256; j++) {
        int i = t + j * 256;
        float v = (i < D) ? h[i] : x[i - D];
        lm = fmaxf(lm, fabsf(v));
    }
    float scale = mkscale(blockMax(lm));
    float rs = 1.0f / scale;
    {
        int gi = k0 + t;
        float v = (gi < D) ? h[gi] : x[gi - D];
        xs[t] = qvalr(v, scale, rs);
    }
    __syncthreads();

    const float2* p = reinterpret_cast<const float2*>(W + (size_t)k0 * D) + (n0 >> 1);
    const int rowstride = D / 2;
    float2 acc = make_float2(0.f, 0.f);
    #pragma unroll 8
    for (int i = 0; i < KC; i++) {
        float2 w = __ldcs(p + (size_t)i * rowstride);   // streaming: read-once weights
        float  xv = xs[i];
        acc.x = fmaf(xv, w.x, acc.x);
        acc.y = fmaf(xv, w.y, acc.y);
    }
    // fire-and-forget accumulation (RED.ADD, no return, no fence, no ticket).
    // Kernel-boundary ordering guarantees visibility to gate_tail_kernel.
    atomicAdd(&g_pre[(size_t)g * D + n0],     acc.x);
    atomicAdd(&g_pre[(size_t)g * D + n0 + 1], acc.y);
}

// ---------------- kernel 2: gate chain (4 blocks) + fused tail in last-done block ----
// Measured 11.8us in this exact form (R12). Reduce is a single float4 load from g_pre.
__global__ void __launch_bounds__(1024, 1)
gate_tail_kernel(const float* __restrict__ bf, const float* __restrict__ bi,
                 const float* __restrict__ bc, const float* __restrict__ bo,
                 const float* __restrict__ c_in, float* __restrict__ out)
{
    const int g = blockIdx.x;
    const float* b = (g == 0) ? bf : (g == 1) ? bi : (g == 2) ? bc : bo;
    const int t = threadIdx.x;

    // preload c + bias (eventual tail winner has them in registers)
    float4 cv = reinterpret_cast<const float4*>(c_in)[t];
    float4 bv = reinterpret_cast<const float4*>(b)[t];

    // combined matmul result: ONE float4 load (accumulation happened in gemv)
    float4 acc = reinterpret_cast<const float4*>(g_pre)[(size_t)g * (D / 4) + t];

    // re-zero own quarter for the next graph replay (1:1 thread->element, no race:
    // only gate g's block touches gate g's quarter; next gemv launch is graph-ordered)
    reinterpret_cast<float4*>(g_pre)[(size_t)g * (D / 4) + t] = make_float4(0.f, 0.f, 0.f, 0.f);

    float2 mm = blockMax2(max4abs(acc), max4abs(bv));
    float sm = mkscale(mm.x), rsm = 1.0f / sm;     // Q(x@w) scale
    float sb = mkscale(mm.y), rsb = 1.0f / sb;     // Q(b) scale

    float y[4] = { qvalr(acc.x, sm, rsm) + qvalr(bv.x, sb, rsb),
                   qvalr(acc.y, sm, rsm) + qvalr(bv.y, sb, rsb),
                   qvalr(acc.z, sm, rsm) + qvalr(bv.z, sb, rsb),
                   qvalr(acc.w, sm, rsm) + qvalr(bv.w, sb, rsb) };

    float lmax = fmaxf(fmaxf(y[0], y[1]), fmaxf(y[2], y[3]));
    float lmin = fminf(fminf(y[0], y[1]), fminf(y[2], y[3]));
    float2 ym = blockMax2(lmax, -lmin);            // (max y, -min y)
    float sy  = mkscale(fmaxf(ym.x, ym.y));
    float rsy = 1.0f / sy;

    // analytic activation scale (monotone functions -> evaluate at argmax)
    float sa;
    if (g == 2) {
        sa = mkscale(tanhf(qvalr(fmaxf(ym.x, ym.y), sy, rsy)));  // tanh odd+monotone
    } else {
        sa = mkscale(sigm(qvalr(ym.x, sy, rsy)));                // sigmoid increasing, >0
    }
    float rsa = 1.0f / sa;

    float4 qa;
    float* qp = &qa.x;
    #pragma unroll
    for (int j = 0; j < 4; j++) {
        float yq = qvalr(y[j], sy, rsy);                 // Q(Q(x@w)+Q(b))
        float a  = (g == 2) ? tanhf(yq) : sigm(yq);
        qp[j] = qvalr(a, sa, rsa);                       // Q(activation)
    }
    reinterpret_cast<float4*>(g_qa)[(size_t)g * (D / 4) + t] = qa;

    // --- last-done handshake: the 4th block to finish runs the tail inline ---
    __shared__ unsigned s_ticket;
    __threadfence();                 // release: qa visible
    __syncthreads();
    if (t == 0) s_ticket = atomicAdd(&g_done, 1u);
    __syncthreads();
    if (s_ticket != 3u) return;
    __threadfence();                 // acquire: other blocks' qa visible

    // --- tail: LSTM state update (this block only; own gate's qa in regs) ---
    const float4* qa4 = reinterpret_cast<const float4*>(g_qa);
    float4 zf = (g == 0) ? qa : qa4[0 * (D / 4) + t];
    float4 zi = (g == 1) ? qa : qa4[1 * (D / 4) + t];
    float4 z  = (g == 2) ? qa : qa4[2 * (D / 4) + t];
    float4 zo = (g == 3) ? qa : qa4[3 * (D / 4) + t];

    float mem[4] = { z.x * zi.x,  z.y * zi.y,  z.z * zi.z,  z.w * zi.w };
    float cf [4] = { cv.x * zf.x, cv.y * zf.y, cv.z * zf.z, cv.w * zf.w };

    float lm = 0.f, lc = 0.f;
    #pragma unroll
    for (int j = 0; j < 4; j++) { lm = fmaxf(lm, fabsf(mem[j])); lc = fmaxf(lc, fabsf(cf[j])); }
    float2 mc = blockMax2(lm, lc);
    float s_mem = mkscale(mc.x), r_mem = 1.0f / s_mem;
    float s_cf  = mkscale(mc.y), r_cf  = 1.0f / s_cf;

    float cn[4]; float ln = 0.f;
    #pragma unroll
    for (int j = 0; j < 4; j++) {
        cn[j] = qvalr(cf[j], s_cf, r_cf) + qvalr(mem[j], s_mem, r_mem);  // Q(c*zf)+Q(z*zi)
        ln = fmaxf(ln, fabsf(cn[j]));
    }
    float cnmax = blockMax(ln);
    float s_cn  = mkscale(cnmax), r_cn = 1.0f / s_cn;

    // analytic: max|tanh(Q(cn))| = tanh(Q(max|cn|))
    float s_t = mkscale(tanhf(qvalr(cnmax, s_cn, r_cn)));
    float r_t = 1.0f / s_t;

    float zop[4] = { zo.x, zo.y, zo.z, zo.w };
    float hv[4]; float lh = 0.f;
    #pragma unroll
    for (int j = 0; j < 4; j++) {
        float cq = qvalr(cn[j], s_cn, r_cn);             // c_new
        float tq = qvalr(tanhf(cq), s_t, r_t);           // Q(tanh(c_new))
        hv[j] = zop[j] * tq;
        lh = fmaxf(lh, fabsf(hv[j]));
    }
    float s_h = mkscale(blockMax(lh)), r_h = 1.0f / s_h;

    float4 o;
    o.x = qvalr(hv[0], s_h, r_h); o.y = qvalr(hv[1], s_h, r_h);
    o.z = qvalr(hv[2], s_h, r_h); o.w = qvalr(hv[3], s_h, r_h);
    reinterpret_cast<float4*>(out)[t] = o;

    // reset handshake for the next graph replay (only this block is alive here)
    __syncthreads();
    if (t == 0) g_done = 0u;
    __threadfence();
}

// ---------------- launch ----------------
extern "C" void kernel_launch(void* const* d_in, const int* in_sizes, int n_in,
                              void* d_out, int out_size)
{
    const float* x  = (const float*)d_in[0];
    const float* c  = (const float*)d_in[1];
    const float* h  = (const float*)d_in[2];
    const float* Wf = (const float*)d_in[3];
    const float* bf = (const float*)d_in[4];
    const float* Wi = (const float*)d_in[5];
    const float* bi = (const float*)d_in[6];
    const float* Wc = (const float*)d_in[7];
    const float* bc = (const float*)d_in[8];
    const float* Wo = (const float*)d_in[9];
    const float* bo = (const float*)d_in[10];

    dim3 gridB(NB, KS, 4);                     // (8, 32, 4) = 1024 blocks
    gemv_kernel<<<gridB, 256>>>(x, h, Wf, Wi, Wc, Wo);

    gate_tail_kernel<<<4, 1024>>>(bf, bi, bc, bo, c, (float*)d_out);
}